// round 13
// baseline (speedup 1.0000x reference)
#include <cuda_runtime.h>

// ---------------------------------------------------------------------------
// DNN_SKalmanNet_GSS — persistent kernel v3: work-stealing phases.
// Ph0: l1/l3 rows (smem input) + gh rows (Whh@hn)      [~146 MB] 22528 tasks
// Ph1: gi rows (Wih @ l1/l3)                           [~252 MB] 12288 tasks
// G  : gate (16 blocks) + out-bias prewrite (2 blocks)
// Ph2: W1 rows (relu)                                  [~67 MB]   8192 tasks
// Ph3: W2 split-K x4 -> atomicAdd d_out                [~34 MB]   8192 tasks
// Warp-per-task; tasks pulled 2-at-a-time from a global atomic counter ->
// near-perfect load balance (fixes the ceil(rows/warps) phase tails that
// capped v2 at 61% DRAM).
// ---------------------------------------------------------------------------

#define H1   5120
#define H2   4096
#define HID  2048
#define IN1  1120

#define NPH0 (2 * H1 + 2 * 3 * HID)   // 22528
#define NPH1 (2 * 3 * HID)            // 12288
#define NPH2 (2 * H2)                 // 8192
#define NPH3 8192                     // 2 br * 1024 rows * 4 chunks

__device__ float g_l1[H1];
__device__ float g_l3[H1];
__device__ float g_gi1[3 * HID];
__device__ float g_gh1[3 * HID];
__device__ float g_gi2[3 * HID];
__device__ float g_gh2[3 * HID];
__device__ float g_h1[HID];
__device__ float g_h2[HID];
__device__ float g_hid1[H2];
__device__ float g_hid2[H2];

__device__ unsigned int g_ctr[8];    // per-phase task counters (zero-init)
__device__ unsigned int g_bar_cnt;
__device__ unsigned int g_bar_gen;

struct Params {
    const float *si, *oi, *ds, *dob, *le, *J;
    const float *l1W, *l1b, *g1Wih, *g1Whh, *g1bih, *g1bhh;
    const float *l2W1, *l2b1, *l2W2, *l2b2;
    const float *l3W, *l3b, *g2Wih, *g2Whh, *g2bih, *g2bhh;
    const float *l4W1, *l4b1, *l4W2, *l4b2;
    const float *hn1, *hn2;
    float* out;
    int nblk;
};

__device__ __forceinline__ void grid_bar(int nblk) {
    __syncthreads();
    if (threadIdx.x == 0) {
        unsigned gen = *(volatile unsigned*)&g_bar_gen;
        __threadfence();
        unsigned old = atomicAdd(&g_bar_cnt, 1u);
        if (old == (unsigned)nblk - 1u) {
            g_bar_cnt = 0u;
            __threadfence();
            *(volatile unsigned*)&g_bar_gen = gen + 1u;
        } else {
            while (*(volatile unsigned*)&g_bar_gen == gen) __nanosleep(32);
        }
        __threadfence();
    }
    __syncthreads();
}

// Warp dot: full value valid on lane 0.
__device__ __forceinline__ float dot_row(const float4* __restrict__ Wr,
                                         const float4* __restrict__ xv,
                                         int c4, int lane) {
    float acc = 0.f;
    #pragma unroll 4
    for (int j = lane; j < c4; j += 32) {
        float4 w = Wr[j];
        float4 x = xv[j];
        acc = fmaf(w.x, x.x, acc);
        acc = fmaf(w.y, x.y, acc);
        acc = fmaf(w.z, x.z, acc);
        acc = fmaf(w.w, x.w, acc);
    }
    #pragma unroll
    for (int o = 16; o; o >>= 1) acc += __shfl_xor_sync(0xffffffffu, acc, o);
    return acc;
}

__device__ __forceinline__ int grab2(unsigned* ctr, int lane) {
    int base = 0;
    if (lane == 0) base = (int)atomicAdd(ctr, 2u);
    return __shfl_sync(0xffffffffu, base, 0);
}

__global__ __launch_bounds__(256, 6) void skn3(Params p) {
    __shared__ float s_in[2][IN1];
    const int lane = threadIdx.x & 31;

    // Build both branch inputs once per block (9 KB smem)
    for (int i = threadIdx.x; i < IN1; i += 256) {
        float v1, v2;
        if (i < 32)       { v1 = p.si[i];      v2 = p.oi[i]; }
        else if (i < 64)  { v1 = p.ds[i - 32]; v2 = p.dob[i - 32]; }
        else if (i < 96)  { v1 = p.le[i - 64]; v2 = v1; }
        else              { v1 = p.J[i - 96];  v2 = v1; }
        s_in[0][i] = v1;
        s_in[1][i] = v2;
    }
    __syncthreads();

    // ---- Ph0: l1/l3 rows + gh rows (work-stealing) ----
    for (;;) {
        int base = grab2(&g_ctr[0], lane);
        if (base >= NPH0) break;
        int lim = base + 2 < NPH0 ? base + 2 : NPH0;
        for (int t = base; t < lim; t++) {
            if (t < 2 * H1) {
                const int br  = t >= H1;
                const int row = t - br * H1;
                const float4* Wr = (const float4*)(br ? p.l3W : p.l1W)
                                   + (size_t)row * (IN1 / 4);
                float a = dot_row(Wr, (const float4*)s_in[br], IN1 / 4, lane);
                if (lane == 0) {
                    float v = a + (br ? p.l3b : p.l1b)[row];
                    (br ? g_l3 : g_l1)[row] = fmaxf(v, 0.f);
                }
            } else {
                const int u   = t - 2 * H1;
                const int br  = u >= 3 * HID;
                const int row = u - br * 3 * HID;
                const float4* Wr = (const float4*)(br ? p.g2Whh : p.g1Whh)
                                   + (size_t)row * (HID / 4);
                float a = dot_row(Wr, (const float4*)(br ? p.hn2 : p.hn1),
                                  HID / 4, lane);
                if (lane == 0)
                    (br ? g_gh2 : g_gh1)[row] = a + (br ? p.g2bhh : p.g1bhh)[row];
            }
        }
    }
    grid_bar(p.nblk);

    // ---- Ph1: gi rows (Wih @ l1/l3) ----
    for (;;) {
        int base = grab2(&g_ctr[1], lane);
        if (base >= NPH1) break;
        int lim = base + 2 < NPH1 ? base + 2 : NPH1;
        for (int t = base; t < lim; t++) {
            const int br  = t >= 3 * HID;
            const int row = t - br * 3 * HID;
            const float4* Wr = (const float4*)(br ? p.g2Wih : p.g1Wih)
                               + (size_t)row * (H1 / 4);
            float a = dot_row(Wr, (const float4*)(br ? g_l3 : g_l1),
                              H1 / 4, lane);
            if (lane == 0)
                (br ? g_gi2 : g_gi1)[row] = a + (br ? p.g2bih : p.g1bih)[row];
        }
    }
    grid_bar(p.nblk);

    // ---- G: gate (blocks 0..15) + output-bias prewrite (16,17) ----
    if (blockIdx.x < 16) {
        const int i  = ((int)blockIdx.x << 8) + threadIdx.x;   // 4096 total
        const int br = (i >= HID);
        const int k  = i - br * HID;
        const float* gi = br ? g_gi2 : g_gi1;
        const float* gh = br ? g_gh2 : g_gh1;
        const float* hp = br ? p.hn2 : p.hn1;
        float*       h  = br ? g_h2 : g_h1;
        float r = 1.f / (1.f + __expf(-(gi[k]       + gh[k])));
        float z = 1.f / (1.f + __expf(-(gi[k + HID] + gh[k + HID])));
        float n = tanhf(gi[k + 2 * HID] + r * gh[k + 2 * HID]);
        h[k] = (1.f - z) * n + z * hp[k];
    } else if (blockIdx.x < 18) {
        const int br = (int)blockIdx.x - 16;
        const float* b2 = br ? p.l4b2 : p.l2b2;
        for (int i = threadIdx.x; i < 1024; i += blockDim.x)
            p.out[br * 1024 + i] = b2[i];
    }
    grid_bar(p.nblk);

    // ---- Ph2: hidden = relu(W1 @ h + b1) ----
    for (;;) {
        int base = grab2(&g_ctr[2], lane);
        if (base >= NPH2) break;
        int lim = base + 2 < NPH2 ? base + 2 : NPH2;
        for (int t = base; t < lim; t++) {
            const int br  = t >= H2;
            const int row = t - br * H2;
            const float4* Wr = (const float4*)(br ? p.l4W1 : p.l2W1)
                               + (size_t)row * (HID / 4);
            float a = dot_row(Wr, (const float4*)(br ? g_h2 : g_h1),
                              HID / 4, lane);
            if (lane == 0) {
                float v = a + (br ? p.l4b1 : p.l2b1)[row];
                (br ? g_hid2 : g_hid1)[row] = fmaxf(v, 0.f);
            }
        }
    }
    grid_bar(p.nblk);

    // ---- Ph3: out += W2 @ hidden (split-K x4, atomics) ----
    for (;;) {
        int base = grab2(&g_ctr[3], lane);
        if (base >= NPH3) break;
        int lim = base + 2 < NPH3 ? base + 2 : NPH3;
        for (int t = base; t < lim; t++) {
            const int br  = t >> 12;
            const int rem = t & 4095;
            const int row = rem >> 2;
            const int q   = rem & 3;
            const float4* Wr = (const float4*)(br ? p.l4W2 : p.l2W2)
                               + (size_t)row * (H2 / 4) + q * 256;
            const float4* xv = (const float4*)(br ? g_hid2 : g_hid1) + q * 256;
            float a = dot_row(Wr, xv, 256, lane);
            if (lane == 0) atomicAdd(&p.out[br * 1024 + row], a);
        }
    }
    grid_bar(p.nblk);

    // Reset counters for the next graph replay (all grabs are done)
    if (blockIdx.x == 0 && threadIdx.x < 8) g_ctr[threadIdx.x] = 0u;
}

extern "C" void kernel_launch(void* const* d_in, const int* in_sizes, int n_in,
                              void* d_out, int out_size) {
    Params p;
    p.si    = (const float*)d_in[0];
    p.oi    = (const float*)d_in[1];
    p.ds    = (const float*)d_in[2];
    p.dob   = (const float*)d_in[3];
    p.le    = (const float*)d_in[4];
    p.J     = (const float*)d_in[5];
    p.l1W   = (const float*)d_in[6];
    p.l1b   = (const float*)d_in[7];
    p.g1Wih = (const float*)d_in[8];
    p.g1Whh = (const float*)d_in[9];
    p.g1bih = (const float*)d_in[10];
    p.g1bhh = (const float*)d_in[11];
    p.l2W1  = (const float*)d_in[12];
    p.l2b1  = (const float*)d_in[13];
    p.l2W2  = (const float*)d_in[14];
    p.l2b2  = (const float*)d_in[15];
    p.l3W   = (const float*)d_in[16];
    p.l3b   = (const float*)d_in[17];
    p.g2Wih = (const float*)d_in[18];
    p.g2Whh = (const float*)d_in[19];
    p.g2bih = (const float*)d_in[20];
    p.g2bhh = (const float*)d_in[21];
    p.l4W1  = (const float*)d_in[22];
    p.l4b1  = (const float*)d_in[23];
    p.l4W2  = (const float*)d_in[24];
    p.l4b2  = (const float*)d_in[25];
    p.hn1   = (const float*)d_in[26];
    p.hn2   = (const float*)d_in[27];
    p.out   = (float*)d_out;

    int dev = 0;
    cudaGetDevice(&dev);
    int numSM = 148;
    cudaDeviceGetAttribute(&numSM, cudaDevAttrMultiProcessorCount, dev);
    int occ = 1;
    cudaOccupancyMaxActiveBlocksPerMultiprocessor(&occ, skn3, 256, 0);
    if (occ < 1) occ = 1;
    if (occ > 8) occ = 8;
    int nblk = occ * numSM;               // all co-resident -> barrier safe
    if (nblk < 32) nblk = 32;             // gate/bias blocks must exist
    p.nblk = nblk;

    skn3<<<nblk, 256>>>(p);
    (void)in_sizes; (void)n_in; (void)out_size;
}

// round 14
// speedup vs baseline: 1.3696x; 1.3696x over previous
#include <cuda_runtime.h>

// ---------------------------------------------------------------------------
// DNN_SKalmanNet_GSS — batch-1 GEMV chain, HBM-bound (~499 MB weights/pass).
// R1 configuration (best measured: 94.2 us) — exact re-bench.
// 6 launches: build_inputs -> l1/l3 -> gru gi/gh (4 segs) -> gate -> l2a/l4a
//             -> l2b/l4b (writes d_out).
// Warp-per-row GEMV, float4 loads, x staged in dynamic shared memory.
// ---------------------------------------------------------------------------

#define XDIM 32
#define YDIM 32
#define H1   5120
#define H2   4096
#define HID  2048
#define IN1  1120
#define OUT1 1024
#define OUT2 1024

// Scratch (device globals: allocation-free)
__device__ float g_input1[IN1];
__device__ float g_input2[IN1];
__device__ float g_l1[H1];
__device__ float g_l3[H1];
__device__ float g_gi1[3 * HID];
__device__ float g_gh1[3 * HID];
__device__ float g_gi2[3 * HID];
__device__ float g_gh2[3 * HID];
__device__ float g_h1[HID];
__device__ float g_h2[HID];
__device__ float g_hid1[H2];
__device__ float g_hid2[H2];

struct Seg {
    const float* W;
    const float* x;
    const float* b;
    float*       y;
    int          rows;
    int          cols;
    int          act;   // 0 = none, 1 = relu
};
struct Segs { Seg s[4]; };

// input1 = [state_inno(32), diff_state(32), lin_err(32), Jacobian(1024)]
// input2 = [obs_inno(32),   diff_obs(32),   lin_err(32), Jacobian(1024)]
__global__ void build_inputs_k(const float* __restrict__ si,
                               const float* __restrict__ oi,
                               const float* __restrict__ ds,
                               const float* __restrict__ dob,
                               const float* __restrict__ le,
                               const float* __restrict__ J) {
    int i = blockIdx.x * blockDim.x + threadIdx.x;
    if (i >= IN1) return;
    float v1, v2;
    if (i < 32)       { v1 = si[i];      v2 = oi[i]; }
    else if (i < 64)  { v1 = ds[i - 32]; v2 = dob[i - 32]; }
    else if (i < 96)  { v1 = le[i - 64]; v2 = v1; }
    else              { v1 = J[i - 96];  v2 = v1; }
    g_input1[i] = v1;
    g_input2[i] = v2;
}

// Multi-segment warp-per-row GEMV. blockIdx.y selects segment.
// Dynamic smem must hold max(cols)*4 bytes for this launch.
__global__ void gemv_multi_k(Segs segs) {
    Seg s = segs.s[blockIdx.y];
    extern __shared__ float4 sx[];
    const int c4 = s.cols >> 2;

    // Stage x into shared memory (conflict-free float4 stride)
    const float4* __restrict__ xv = (const float4*)s.x;
    for (int j = threadIdx.x; j < c4; j += blockDim.x) sx[j] = xv[j];
    __syncthreads();

    const int lane = threadIdx.x & 31;
    const int warp = (blockIdx.x * blockDim.x + threadIdx.x) >> 5;
    const int nw   = (gridDim.x * blockDim.x) >> 5;

    for (int row = warp; row < s.rows; row += nw) {
        const float4* __restrict__ Wr = (const float4*)s.W + (size_t)row * c4;
        float acc = 0.f;
        #pragma unroll 4
        for (int j = lane; j < c4; j += 32) {
            float4 w  = Wr[j];
            float4 xx = sx[j];
            acc = fmaf(w.x, xx.x, acc);
            acc = fmaf(w.y, xx.y, acc);
            acc = fmaf(w.z, xx.z, acc);
            acc = fmaf(w.w, xx.w, acc);
        }
        #pragma unroll
        for (int o = 16; o; o >>= 1) acc += __shfl_xor_sync(0xffffffffu, acc, o);
        if (lane == 0) {
            float v = acc + s.b[row];
            if (s.act) v = fmaxf(v, 0.f);
            s.y[row] = v;
        }
    }
}

__device__ __forceinline__ float sigmoidf_(float x) {
    return 1.f / (1.f + __expf(-x));
}

// PyTorch GRU gate combine (order r,z,n): h' = (1-z)*n + z*h
__global__ void gru_gate_k(const float* __restrict__ hn1,
                           const float* __restrict__ hn2) {
    int i = blockIdx.x * blockDim.x + threadIdx.x;
    if (i >= HID) return;
    const float* gi; const float* gh; const float* hp; float* h;
    if (blockIdx.y == 0) { gi = g_gi1; gh = g_gh1; hp = hn1; h = g_h1; }
    else                 { gi = g_gi2; gh = g_gh2; hp = hn2; h = g_h2; }
    float r = sigmoidf_(gi[i]           + gh[i]);
    float z = sigmoidf_(gi[i + HID]     + gh[i + HID]);
    float n = tanhf(gi[i + 2 * HID] + r * gh[i + 2 * HID]);
    h[i] = (1.f - z) * n + z * hp[i];
}

static inline Seg mkseg(const float* W, const float* x, const float* b, float* y,
                        int rows, int cols, int act) {
    Seg s; s.W = W; s.x = x; s.b = b; s.y = y; s.rows = rows; s.cols = cols; s.act = act;
    return s;
}

extern "C" void kernel_launch(void* const* d_in, const int* in_sizes, int n_in,
                              void* d_out, int out_size) {
    // Inputs in reference-signature order
    const float* state_inno = (const float*)d_in[0];
    const float* obs_inno   = (const float*)d_in[1];
    const float* diff_state = (const float*)d_in[2];
    const float* diff_obs   = (const float*)d_in[3];
    const float* lin_err    = (const float*)d_in[4];
    const float* Jacobian   = (const float*)d_in[5];
    const float* l1_W  = (const float*)d_in[6];
    const float* l1_b  = (const float*)d_in[7];
    const float* g1Wih = (const float*)d_in[8];
    const float* g1Whh = (const float*)d_in[9];
    const float* g1bih = (const float*)d_in[10];
    const float* g1bhh = (const float*)d_in[11];
    const float* l2_W1 = (const float*)d_in[12];
    const float* l2_b1 = (const float*)d_in[13];
    const float* l2_W2 = (const float*)d_in[14];
    const float* l2_b2 = (const float*)d_in[15];
    const float* l3_W  = (const float*)d_in[16];
    const float* l3_b  = (const float*)d_in[17];
    const float* g2Wih = (const float*)d_in[18];
    const float* g2Whh = (const float*)d_in[19];
    const float* g2bih = (const float*)d_in[20];
    const float* g2bhh = (const float*)d_in[21];
    const float* l4_W1 = (const float*)d_in[22];
    const float* l4_b1 = (const float*)d_in[23];
    const float* l4_W2 = (const float*)d_in[24];
    const float* l4_b2 = (const float*)d_in[25];
    const float* hn1   = (const float*)d_in[26];
    const float* hn2   = (const float*)d_in[27];

    float* out = (float*)d_out;   // [Pk(1024), Sk(1024)]

    // Device addresses of scratch symbols (capture-safe: not a stream op)
    float *p_in1, *p_in2, *p_l1, *p_l3;
    float *p_gi1, *p_gh1, *p_gi2, *p_gh2, *p_h1, *p_h2, *p_hid1, *p_hid2;
    cudaGetSymbolAddress((void**)&p_in1,  g_input1);
    cudaGetSymbolAddress((void**)&p_in2,  g_input2);
    cudaGetSymbolAddress((void**)&p_l1,   g_l1);
    cudaGetSymbolAddress((void**)&p_l3,   g_l3);
    cudaGetSymbolAddress((void**)&p_gi1,  g_gi1);
    cudaGetSymbolAddress((void**)&p_gh1,  g_gh1);
    cudaGetSymbolAddress((void**)&p_gi2,  g_gi2);
    cudaGetSymbolAddress((void**)&p_gh2,  g_gh2);
    cudaGetSymbolAddress((void**)&p_h1,   g_h1);
    cudaGetSymbolAddress((void**)&p_h2,   g_h2);
    cudaGetSymbolAddress((void**)&p_hid1, g_hid1);
    cudaGetSymbolAddress((void**)&p_hid2, g_hid2);

    const Seg z = mkseg(nullptr, nullptr, nullptr, nullptr, 0, 0, 0);

    // 1) concat inputs
    build_inputs_k<<<(IN1 + 255) / 256, 256>>>(state_inno, obs_inno, diff_state,
                                               diff_obs, lin_err, Jacobian);

    // 2) l1_out = relu(l1_W @ in1 + b) ; l3_out = relu(l3_W @ in2 + b)
    {
        Segs sg;
        sg.s[0] = mkseg(l1_W, p_in1, l1_b, p_l1, H1, IN1, 1);
        sg.s[1] = mkseg(l3_W, p_in2, l3_b, p_l3, H1, IN1, 1);
        sg.s[2] = z; sg.s[3] = z;
        gemv_multi_k<<<dim3(H1 / 8, 2), 256, IN1 * sizeof(float)>>>(sg);
    }

    // 3) GRU pre-gates: gi = Wih@l_out + bih ; gh = Whh@hn + bhh (both branches)
    {
        Segs sg;
        sg.s[0] = mkseg(g1Wih, p_l1, g1bih, p_gi1, 3 * HID, H1,  0);
        sg.s[1] = mkseg(g1Whh, hn1,  g1bhh, p_gh1, 3 * HID, HID, 0);
        sg.s[2] = mkseg(g2Wih, p_l3, g2bih, p_gi2, 3 * HID, H1,  0);
        sg.s[3] = mkseg(g2Whh, hn2,  g2bhh, p_gh2, 3 * HID, HID, 0);
        gemv_multi_k<<<dim3((3 * HID) / 8, 4), 256, H1 * sizeof(float)>>>(sg);
    }

    // 4) gate combine -> h1, h2
    gru_gate_k<<<dim3(HID / 256, 2), 256>>>(hn1, hn2);

    // 5) hidden = relu(W1 @ h + b1) (both branches)
    {
        Segs sg;
        sg.s[0] = mkseg(l2_W1, p_h1, l2_b1, p_hid1, H2, HID, 1);
        sg.s[1] = mkseg(l4_W1, p_h2, l4_b1, p_hid2, H2, HID, 1);
        sg.s[2] = z; sg.s[3] = z;
        gemv_multi_k<<<dim3(H2 / 8, 2), 256, HID * sizeof(float)>>>(sg);
    }

    // 6) Pk = W2 @ hidden + b2 ; Sk likewise -> d_out
    {
        Segs sg;
        sg.s[0] = mkseg(l2_W2, p_hid1, l2_b2, out,        OUT1, H2, 0);
        sg.s[1] = mkseg(l4_W2, p_hid2, l4_b2, out + OUT1, OUT2, H2, 0);
        sg.s[2] = z; sg.s[3] = z;
        gemv_multi_k<<<dim3(OUT1 / 8, 2), 256, H2 * sizeof(float)>>>(sg);
    }
    (void)in_sizes; (void)n_in; (void)out_size;
}